// round 2
// baseline (speedup 1.0000x reference)
#include <cuda_runtime.h>
#include <stdint.h>
#include <math.h>

// Problem constants
#define BS   4096
#define NE   128
#define NQ   32
#define IND  256
#define EMB  512
#define NH   4
#define HD   128

// -------- scratch (static device globals; no runtime allocation) --------
__device__ float g_k [BS * NE * EMB];   // [b][e][512]  k features
__device__ float g_v [BS * NE * EMB];   // [b][e][512]  v features
__device__ float g_q [BS * NQ * EMB];   // [b][qi][512] q features
__device__ float g_ao[BS * NQ * EMB];   // [b][qi][512] attention output
__device__ uint8_t g_pre [BS * NQ * NE]; // normalized pre_mask (0/1 bytes)
__device__ uint8_t g_post[BS * NQ];      // normalized post_mask
__device__ int     g_mask_kind;          // 0=uint8, 1=int32, 2=float32

// -------- packed f32x2 helpers (ptxas will not auto-fuse these) --------
__device__ __forceinline__ unsigned long long pk2(float lo, float hi) {
    unsigned long long r;
    asm("mov.b64 %0, {%1, %2};" : "=l"(r) : "f"(lo), "f"(hi));
    return r;
}
__device__ __forceinline__ void upk2(unsigned long long p, float& lo, float& hi) {
    asm("mov.b64 {%0, %1}, %2;" : "=f"(lo), "=f"(hi) : "l"(p));
}
__device__ __forceinline__ unsigned long long fma2_(unsigned long long a,
                                                    unsigned long long b,
                                                    unsigned long long c) {
    unsigned long long d;
    asm("fma.rn.f32x2 %0, %1, %2, %3;" : "=l"(d) : "l"(a), "l"(b), "l"(c));
    return d;
}

// ============================================================================
// Mask dtype sniffer + normalizer.
// uint8 0/1 data: 4-byte words frequently have bytes 1..3 nonzero.
// int32 0/1 data: every word is 0 or 1 (no high bytes).
// float32 0/1 data: words are 0 or 0x3F800000.
// ============================================================================
__global__ void sniff_kernel(const void* __restrict__ pre)
{
    __shared__ int s_hasF, s_hasHi;
    if (threadIdx.x == 0) { s_hasF = 0; s_hasHi = 0; }
    __syncthreads();
    const unsigned* w = (const unsigned*)pre;
    int hasF = 0, hasHi = 0;
    for (int i = threadIdx.x; i < 16384; i += blockDim.x) {   // first 64KB
        const unsigned v = w[i];
        if (v == 0x3F800000u) hasF = 1;
        if (v & 0xFFFFFF00u)  hasHi = 1;
    }
    if (hasF)  atomicOr(&s_hasF, 1);
    if (hasHi) atomicOr(&s_hasHi, 1);
    __syncthreads();
    if (threadIdx.x == 0)
        g_mask_kind = s_hasF ? 2 : (s_hasHi ? 0 : 1);
}

__global__ void cvt_mask_kernel(const void* __restrict__ src,
                                uint8_t* __restrict__ dst, int n)
{
    const int i = blockIdx.x * blockDim.x + threadIdx.x;
    if (i >= n) return;
    const int k = g_mask_kind;
    uint8_t v;
    if (k == 0)      v = (((const uint8_t*)src)[i] != 0);
    else if (k == 1) v = (((const int*)src)[i] != 0);
    else             v = (((const float*)src)[i] != 0.f);
    dst[i] = v;
}

// ============================================================================
// Generic tiled GEMM:  C[M,N] = A[M,K] @ W[N,K]^T   (W row-major [N,K])
// 128x128 tile, BK=16, 256 threads, 8x8 register tiles, strided mapping
// (m = ty+16i, n = tx+16j) -> conflict-free smem reads; fma.rn.f32x2 core.
// MODE 0: KV pass  — A=entities, N=1024: n<512 -> g_k else g_v
// MODE 1: Q  pass  — A=entities with row remap (b*NE + qi) -> g_q
// MODE 2: OUT pass — A=g_ao -> Cout with bias + post_mask epilogue
// ============================================================================
template<int KDIM, int MODE>
__global__ __launch_bounds__(256, 2)
void gemm_kernel(const float* __restrict__ A,
                 const float* __restrict__ W,
                 float* __restrict__ Cout,
                 const float* __restrict__ bias)
{
    constexpr int BK   = 16;
    constexpr int SSTR = 132;
    __shared__ float As[BK][SSTR];   // As[k][m]
    __shared__ float Bs[BK][SSTR];   // Bs[k][n]

    const int t  = threadIdx.x;
    const int tx = t & 15;
    const int ty = t >> 4;
    const int mtile = blockIdx.y;
    const int ntile = blockIdx.x;

    const float* Aptr = (MODE == 2) ? (const float*)g_ao : A;

    unsigned long long acc2[8][4];
    #pragma unroll
    for (int i = 0; i < 8; i++)
        #pragma unroll
        for (int j = 0; j < 4; j++) acc2[i][j] = 0ull;

    for (int kt = 0; kt < KDIM; kt += BK) {
        __syncthreads();
        #pragma unroll
        for (int l = 0; l < 2; l++) {
            const int idx = t + l * 256;
            const int m   = idx >> 2;
            const int kq  = (idx & 3) * 4;
            const int gm  = mtile * 128 + m;
            const int arow = (MODE == 1) ? ((gm >> 5) * NE + (gm & 31)) : gm;
            const float4 av = *reinterpret_cast<const float4*>(
                Aptr + (size_t)arow * KDIM + kt + kq);
            As[kq + 0][m] = av.x; As[kq + 1][m] = av.y;
            As[kq + 2][m] = av.z; As[kq + 3][m] = av.w;

            const int n = m;
            const float4 bv = *reinterpret_cast<const float4*>(
                W + (size_t)(ntile * 128 + n) * KDIM + kt + kq);
            Bs[kq + 0][n] = bv.x; Bs[kq + 1][n] = bv.y;
            Bs[kq + 2][n] = bv.z; Bs[kq + 3][n] = bv.w;
        }
        __syncthreads();

        #pragma unroll
        for (int k = 0; k < BK; k++) {
            float a[8], bf[8];
            #pragma unroll
            for (int i = 0; i < 8; i++) a[i]  = As[k][ty + 16 * i];
            #pragma unroll
            for (int j = 0; j < 8; j++) bf[j] = Bs[k][tx + 16 * j];
            unsigned long long b2[4];
            #pragma unroll
            for (int j = 0; j < 4; j++) b2[j] = pk2(bf[2 * j], bf[2 * j + 1]);
            #pragma unroll
            for (int i = 0; i < 8; i++) {
                const unsigned long long a2 = pk2(a[i], a[i]);
                #pragma unroll
                for (int j = 0; j < 4; j++)
                    acc2[i][j] = fma2_(a2, b2[j], acc2[i][j]);
            }
        }
    }

    #pragma unroll
    for (int i = 0; i < 8; i++) {
        const int gm = mtile * 128 + ty + 16 * i;
        #pragma unroll
        for (int j4 = 0; j4 < 4; j4++) {
            float vlo, vhi;
            upk2(acc2[i][j4], vlo, vhi);
            #pragma unroll
            for (int h = 0; h < 2; h++) {
                const int j  = 2 * j4 + h;
                const int gn = ntile * 128 + tx + 16 * j;
                float v = (h == 0) ? vlo : vhi;
                if (MODE == 0) {
                    if (gn < EMB) g_k[(size_t)gm * EMB + gn] = v;
                    else          g_v[(size_t)gm * EMB + (gn - EMB)] = v;
                } else if (MODE == 1) {
                    g_q[(size_t)gm * EMB + gn] = v;
                } else {
                    v += bias[gn];
                    if (g_post[gm]) v = 0.f;
                    Cout[(size_t)gm * EMB + gn] = v;
                }
            }
        }
    }
}

// ============================================================================
// Attention: one CTA per (batch, head). 256 threads.
// smem: q[32][129] | kv[128][129] (k reused for v) | logits[32][129]
// ============================================================================
#define SST 129
#define ATTN_SMEM ((32 + 128 + 32) * SST * 4)

__global__ __launch_bounds__(256)
void attn_kernel()
{
    const int b = blockIdx.x;
    const int h = blockIdx.y;
    extern __shared__ float sm[];
    float* qs = sm;                    // 32  x 129
    float* kv = sm + 32 * SST;         // 128 x 129
    float* ls = sm + (32 + 128) * SST; // 32  x 129

    const int t  = threadIdx.x;
    const int tx = t & 31;
    const int ty = t >> 5;

    #pragma unroll
    for (int l = 0; l < 4; l++) {
        const int idx = t + l * 256;
        const int qi  = idx >> 5;
        const int dq  = (idx & 31) * 4;
        const float4 v = *reinterpret_cast<const float4*>(
            &g_q[(size_t)(b * NQ + qi) * EMB + h * HD + dq]);
        qs[qi * SST + dq + 0] = v.x; qs[qi * SST + dq + 1] = v.y;
        qs[qi * SST + dq + 2] = v.z; qs[qi * SST + dq + 3] = v.w;
    }
    #pragma unroll
    for (int l = 0; l < 16; l++) {
        const int idx = t + l * 256;
        const int kj  = idx >> 5;
        const int dq  = (idx & 31) * 4;
        const float4 v = *reinterpret_cast<const float4*>(
            &g_k[(size_t)(b * NE + kj) * EMB + h * HD + dq]);
        kv[kj * SST + dq + 0] = v.x; kv[kj * SST + dq + 1] = v.y;
        kv[kj * SST + dq + 2] = v.z; kv[kj * SST + dq + 3] = v.w;
    }
    __syncthreads();

    // logits[32,128] = q @ k^T / sqrt(HD), masked
    float acc[4][4];
    #pragma unroll
    for (int i = 0; i < 4; i++)
        #pragma unroll
        for (int j = 0; j < 4; j++) acc[i][j] = 0.f;

    for (int d = 0; d < HD; d++) {
        float a[4], bb[4];
        #pragma unroll
        for (int i = 0; i < 4; i++) a[i]  = qs[(ty + 8 * i) * SST + d];
        #pragma unroll
        for (int j = 0; j < 4; j++) bb[j] = kv[(tx + 32 * j) * SST + d];
        #pragma unroll
        for (int i = 0; i < 4; i++)
            #pragma unroll
            for (int j = 0; j < 4; j++)
                acc[i][j] = fmaf(a[i], bb[j], acc[i][j]);
    }

    const float inv_scale = 0.08838834764831845f;  // 1/sqrt(128)
    const uint8_t* pm = g_pre + (size_t)b * NQ * NE;
    #pragma unroll
    for (int i = 0; i < 4; i++) {
        const int qi = ty + 8 * i;
        #pragma unroll
        for (int j = 0; j < 4; j++) {
            const int kj = tx + 32 * j;
            ls[qi * SST + kj] = pm[qi * NE + kj] ? -1e30f : acc[i][j] * inv_scale;
        }
    }
    __syncthreads();

    // load v tile (overlaps with softmax)
    #pragma unroll
    for (int l = 0; l < 16; l++) {
        const int idx = t + l * 256;
        const int kj  = idx >> 5;
        const int dq  = (idx & 31) * 4;
        const float4 v = *reinterpret_cast<const float4*>(
            &g_v[(size_t)(b * NE + kj) * EMB + h * HD + dq]);
        kv[kj * SST + dq + 0] = v.x; kv[kj * SST + dq + 1] = v.y;
        kv[kj * SST + dq + 2] = v.z; kv[kj * SST + dq + 3] = v.w;
    }

    // row softmax: warp w -> rows 4w..4w+3
    {
        const int w    = t >> 5;
        const int lane = t & 31;
        #pragma unroll
        for (int rr = 0; rr < 4; rr++) {
            const int r = w * 4 + rr;
            float x0 = ls[r * SST + lane];
            float x1 = ls[r * SST + lane + 32];
            float x2 = ls[r * SST + lane + 64];
            float x3 = ls[r * SST + lane + 96];
            float mx = fmaxf(fmaxf(x0, x1), fmaxf(x2, x3));
            #pragma unroll
            for (int off = 16; off; off >>= 1)
                mx = fmaxf(mx, __shfl_xor_sync(0xffffffffu, mx, off));
            float e0 = (x0 <= -1e29f) ? 0.f : expf(x0 - mx);
            float e1 = (x1 <= -1e29f) ? 0.f : expf(x1 - mx);
            float e2 = (x2 <= -1e29f) ? 0.f : expf(x2 - mx);
            float e3 = (x3 <= -1e29f) ? 0.f : expf(x3 - mx);
            float s = e0 + e1 + e2 + e3;
            #pragma unroll
            for (int off = 16; off; off >>= 1)
                s += __shfl_xor_sync(0xffffffffu, s, off);
            const float inv = (s > 0.f) ? (1.f / s) : 0.f;
            ls[r * SST + lane]      = e0 * inv;
            ls[r * SST + lane + 32] = e1 * inv;
            ls[r * SST + lane + 64] = e2 * inv;
            ls[r * SST + lane + 96] = e3 * inv;
        }
    }
    __syncthreads();

    // out[32,128] = attn @ v
    float o[4][4];
    #pragma unroll
    for (int i = 0; i < 4; i++)
        #pragma unroll
        for (int j = 0; j < 4; j++) o[i][j] = 0.f;

    for (int kj = 0; kj < NE; kj++) {
        float a[4], bb[4];
        #pragma unroll
        for (int i = 0; i < 4; i++) a[i]  = ls[(ty + 8 * i) * SST + kj];
        #pragma unroll
        for (int j = 0; j < 4; j++) bb[j] = kv[kj * SST + tx + 32 * j];
        #pragma unroll
        for (int i = 0; i < 4; i++)
            #pragma unroll
            for (int j = 0; j < 4; j++)
                o[i][j] = fmaf(a[i], bb[j], o[i][j]);
    }

    #pragma unroll
    for (int i = 0; i < 4; i++) {
        const int qi = ty + 8 * i;
        #pragma unroll
        for (int j = 0; j < 4; j++) {
            const int d = tx + 32 * j;
            g_ao[(size_t)(b * NQ + qi) * EMB + h * HD + d] = o[i][j];
        }
    }
}

// ============================================================================
extern "C" void kernel_launch(void* const* d_in, const int* in_sizes, int n_in,
                              void* d_out, int out_size)
{
    // Identify inputs by element count (all six are distinct) — robust to
    // any metadata ordering.
    const float *entities = nullptr, *W_in = nullptr, *W_out = nullptr,
                *b_out = nullptr;
    const void  *pre_mask = nullptr, *post_mask = nullptr;
    for (int i = 0; i < n_in; i++) {
        switch (in_sizes[i]) {
            case BS * NE * IND:   entities  = (const float*)d_in[i]; break; // 134217728
            case BS * NQ * NE:    pre_mask  = d_in[i];               break; // 16777216
            case BS * NQ:         post_mask = d_in[i];               break; // 131072
            case 3 * EMB * IND:   W_in      = (const float*)d_in[i]; break; // 393216
            case EMB * EMB:       W_out     = (const float*)d_in[i]; break; // 262144
            case EMB:             b_out     = (const float*)d_in[i]; break; // 512
        }
    }
    float* out = (float*)d_out;

    cudaFuncSetAttribute(attn_kernel,
                         cudaFuncAttributeMaxDynamicSharedMemorySize, ATTN_SMEM);

    // 0) normalize masks to uint8 (dtype-agnostic)
    sniff_kernel<<<1, 256>>>(pre_mask);
    {
        uint8_t* pre_dst; cudaGetSymbolAddress((void**)&pre_dst, g_pre);
        uint8_t* post_dst; cudaGetSymbolAddress((void**)&post_dst, g_post);
        cvt_mask_kernel<<<(BS * NQ * NE + 255) / 256, 256>>>(pre_mask, pre_dst,
                                                             BS * NQ * NE);
        cvt_mask_kernel<<<(BS * NQ + 255) / 256, 256>>>(post_mask, post_dst,
                                                        BS * NQ);
    }

    // 1) K,V projection -> g_k, g_v
    gemm_kernel<IND, 0><<<dim3(8, BS), 256>>>(
        entities, W_in + (size_t)EMB * IND, nullptr, nullptr);

    // 2) Q projection -> g_q
    gemm_kernel<IND, 1><<<dim3(4, (BS * NQ) / 128), 256>>>(
        entities, W_in, nullptr, nullptr);

    // 3) masked multi-head attention -> g_ao
    attn_kernel<<<dim3(BS, NH), 256, ATTN_SMEM>>>();

    // 4) output projection + bias + post_mask -> d_out
    gemm_kernel<EMB, 2><<<dim3(4, (BS * NQ) / 128), 256>>>(
        nullptr, W_out, out, b_out);
}

// round 4
// speedup vs baseline: 1.8936x; 1.8936x over previous
#include <cuda_runtime.h>
#include <cuda_bf16.h>
#include <stdint.h>
#include <math.h>

// Problem constants
#define BS   4096
#define NE   128
#define NQ   32
#define IND  256
#define EMB  512
#define NH   4
#define HD   128

// -------- scratch (static device globals; no runtime allocation) --------
__device__ float g_k [BS * NE * EMB];
__device__ float g_v [BS * NE * EMB];
__device__ float g_q [BS * NQ * EMB];
__device__ float g_ao[BS * NQ * EMB];
__device__ uint8_t g_pre [BS * NQ * NE];
__device__ uint8_t g_post[BS * NQ];
__device__ int     g_mask_kind;

// ============================================================================
// Mask dtype sniffer + normalizer (proven in R2)
// ============================================================================
__global__ void sniff_kernel(const void* __restrict__ pre)
{
    __shared__ int s_hasF, s_hasHi;
    if (threadIdx.x == 0) { s_hasF = 0; s_hasHi = 0; }
    __syncthreads();
    const unsigned* w = (const unsigned*)pre;
    int hasF = 0, hasHi = 0;
    for (int i = threadIdx.x; i < 16384; i += blockDim.x) {
        const unsigned v = w[i];
        if (v == 0x3F800000u) hasF = 1;
        if (v & 0xFFFFFF00u)  hasHi = 1;
    }
    if (hasF)  atomicOr(&s_hasF, 1);
    if (hasHi) atomicOr(&s_hasHi, 1);
    __syncthreads();
    if (threadIdx.x == 0)
        g_mask_kind = s_hasF ? 2 : (s_hasHi ? 0 : 1);
}

__global__ void cvt_mask_kernel(const void* __restrict__ src,
                                uint8_t* __restrict__ dst, int n)
{
    const int i = blockIdx.x * blockDim.x + threadIdx.x;
    if (i >= n) return;
    const int k = g_mask_kind;
    uint8_t v;
    if (k == 0)      v = (((const uint8_t*)src)[i] != 0);
    else if (k == 1) v = (((const int*)src)[i] != 0);
    else             v = (((const float*)src)[i] != 0.f);
    dst[i] = v;
}

// ============================================================================
// bf16 3x-split GEMM on mma.sync (portable PTX -> HMMA tensor pipe).
//   C[M,N] = A[M,K] @ W[N,K]^T, fp32 in/out, fp32 accumulate.
//   x = hi + lo (bf16 each); C ~= Ah*Bh + Ah*Bl + Al*Bh  (error ~1e-5)
// Tile 128x128, BK=32, 256 threads = 8 warps in 2(M) x 4(N); warp: 64x32.
// smem pair-arrays stride 20 words/row -> conflict-free fragment LDS.
// MODE 0: KV (N=1024 -> g_k / g_v)  MODE 1: Q (row gather)  MODE 2: out-proj
// ============================================================================
#define SR 20   // smem row stride in uint32 (16 pairs used + 4 pad)

__device__ __forceinline__ void mma_bf16(float* d, const uint32_t* a,
                                         const uint32_t* b)
{
    asm volatile(
        "mma.sync.aligned.m16n8k16.row.col.f32.bf16.bf16.f32 "
        "{%0,%1,%2,%3}, {%4,%5,%6,%7}, {%8,%9}, {%0,%1,%2,%3};"
        : "+f"(d[0]), "+f"(d[1]), "+f"(d[2]), "+f"(d[3])
        : "r"(a[0]), "r"(a[1]), "r"(a[2]), "r"(a[3]), "r"(b[0]), "r"(b[1]));
}

// split one float4 (4 consecutive k-values) into 2 hi-pair + 2 lo-pair words
__device__ __forceinline__ void cvt_store(uint32_t* __restrict__ H,
                                          uint32_t* __restrict__ L,
                                          int base, float4 v)
{
    __nv_bfloat162 h0 = __floats2bfloat162_rn(v.x, v.y);   // .x = low half
    __nv_bfloat162 h1 = __floats2bfloat162_rn(v.z, v.w);
    float hx = __bfloat162float(h0.x), hy = __bfloat162float(h0.y);
    float hz = __bfloat162float(h1.x), hw = __bfloat162float(h1.y);
    __nv_bfloat162 l0 = __floats2bfloat162_rn(v.x - hx, v.y - hy);
    __nv_bfloat162 l1 = __floats2bfloat162_rn(v.z - hz, v.w - hw);
    H[base + 0] = *reinterpret_cast<uint32_t*>(&h0);
    H[base + 1] = *reinterpret_cast<uint32_t*>(&h1);
    L[base + 0] = *reinterpret_cast<uint32_t*>(&l0);
    L[base + 1] = *reinterpret_cast<uint32_t*>(&l1);
}

template<int KDIM, int MODE>
__device__ __forceinline__ void load_frag(const float* __restrict__ Ap,
                                          const float* __restrict__ W,
                                          int mtile, int ntile, int s, int t,
                                          float4* a4, float4* b4)
{
    #pragma unroll
    for (int l = 0; l < 4; l++) {
        const int idx = t + l * 256;
        const int r  = idx >> 3;              // 0..127
        const int qc = idx & 7;               // float4 col (32 floats/row)
        const int gm = mtile * 128 + r;
        const int arow = (MODE == 1) ? ((gm >> 5) * NE + (gm & 31)) : gm;
        a4[l] = *reinterpret_cast<const float4*>(
            Ap + (size_t)arow * KDIM + s * 32 + qc * 4);
        b4[l] = *reinterpret_cast<const float4*>(
            W + (size_t)(ntile * 128 + r) * KDIM + s * 32 + qc * 4);
    }
}

template<int KDIM, int MODE>
__global__ __launch_bounds__(256)
void mma_gemm(const float* __restrict__ A,
              const float* __restrict__ W,
              float* __restrict__ Cout,
              const float* __restrict__ bias)
{
    constexpr int S = KDIM / 32;
    __shared__ uint32_t Ah[128 * SR], Al[128 * SR];
    __shared__ uint32_t Bh[128 * SR], Bl[128 * SR];

    const int t    = threadIdx.x;
    const int lane = t & 31;
    const int wid  = t >> 5;
    const int wm   = wid >> 2;          // 0..1  (M)
    const int wn   = wid & 3;           // 0..3  (N)
    const int ntile = blockIdx.x;
    const int mtile = blockIdx.y;

    const float* Ap = (MODE == 2) ? (const float*)g_ao : A;

    float acc[4][4][4];
    #pragma unroll
    for (int i = 0; i < 4; i++)
        #pragma unroll
        for (int j = 0; j < 4; j++)
            #pragma unroll
            for (int c = 0; c < 4; c++) acc[i][j][c] = 0.f;

    float4 a4[4], b4[4];
    load_frag<KDIM, MODE>(Ap, W, mtile, ntile, 0, t, a4, b4);

    const int rq = lane >> 2;           // 0..7
    const int pq = lane & 3;            // 0..3

    for (int s = 0; s < S; s++) {
        if (s) __syncthreads();         // compute done before overwrite
        #pragma unroll
        for (int l = 0; l < 4; l++) {
            const int idx = t + l * 256;
            const int r  = idx >> 3;
            const int qc = idx & 7;
            cvt_store(Ah, Al, r * SR + 2 * qc, a4[l]);
            cvt_store(Bh, Bl, r * SR + 2 * qc, b4[l]);
        }
        if (s + 1 < S)
            load_frag<KDIM, MODE>(Ap, W, mtile, ntile, s + 1, t, a4, b4);
        __syncthreads();

        #pragma unroll
        for (int kh = 0; kh < 2; kh++) {
            const int p = kh * 8 + pq;
            uint32_t bh[4][2], bl[4][2];
            #pragma unroll
            for (int nf = 0; nf < 4; nf++) {
                const int row = wn * 32 + nf * 8 + rq;
                bh[nf][0] = Bh[row * SR + p];
                bh[nf][1] = Bh[row * SR + p + 4];
                bl[nf][0] = Bl[row * SR + p];
                bl[nf][1] = Bl[row * SR + p + 4];
            }
            uint32_t ah[4][4], al[4][4];
            #pragma unroll
            for (int mf = 0; mf < 4; mf++) {
                const int r0 = wm * 64 + mf * 16 + rq;
                const int r8 = r0 + 8;
                ah[mf][0] = Ah[r0 * SR + p];
                ah[mf][1] = Ah[r8 * SR + p];
                ah[mf][2] = Ah[r0 * SR + p + 4];
                ah[mf][3] = Ah[r8 * SR + p + 4];
                al[mf][0] = Al[r0 * SR + p];
                al[mf][1] = Al[r8 * SR + p];
                al[mf][2] = Al[r0 * SR + p + 4];
                al[mf][3] = Al[r8 * SR + p + 4];
            }
            #pragma unroll
            for (int mf = 0; mf < 4; mf++)
                #pragma unroll
                for (int nf = 0; nf < 4; nf++) {
                    mma_bf16(acc[mf][nf], ah[mf], bh[nf]);
                    mma_bf16(acc[mf][nf], ah[mf], bl[nf]);
                    mma_bf16(acc[mf][nf], al[mf], bh[nf]);
                }
        }
    }

    // ---- epilogue: write fp32 results (float2 per fragment half) ----
    #pragma unroll
    for (int mf = 0; mf < 4; mf++) {
        #pragma unroll
        for (int nf = 0; nf < 4; nf++) {
            const int r0 = mtile * 128 + wm * 64 + mf * 16 + rq;
            const int r1 = r0 + 8;
            const int gn = ntile * 128 + wn * 32 + nf * 8 + pq * 2;
            float2 v0 = make_float2(acc[mf][nf][0], acc[mf][nf][1]);
            float2 v1 = make_float2(acc[mf][nf][2], acc[mf][nf][3]);
            if (MODE == 0) {
                if (gn < EMB) {
                    *reinterpret_cast<float2*>(&g_k[(size_t)r0 * EMB + gn]) = v0;
                    *reinterpret_cast<float2*>(&g_k[(size_t)r1 * EMB + gn]) = v1;
                } else {
                    *reinterpret_cast<float2*>(&g_v[(size_t)r0 * EMB + gn - EMB]) = v0;
                    *reinterpret_cast<float2*>(&g_v[(size_t)r1 * EMB + gn - EMB]) = v1;
                }
            } else if (MODE == 1) {
                *reinterpret_cast<float2*>(&g_q[(size_t)r0 * EMB + gn]) = v0;
                *reinterpret_cast<float2*>(&g_q[(size_t)r1 * EMB + gn]) = v1;
            } else {
                const float2 bb = *reinterpret_cast<const float2*>(&bias[gn]);
                v0.x += bb.x; v0.y += bb.y;
                v1.x += bb.x; v1.y += bb.y;
                if (g_post[r0]) { v0.x = 0.f; v0.y = 0.f; }
                if (g_post[r1]) { v1.x = 0.f; v1.y = 0.f; }
                *reinterpret_cast<float2*>(&Cout[(size_t)r0 * EMB + gn]) = v0;
                *reinterpret_cast<float2*>(&Cout[(size_t)r1 * EMB + gn]) = v1;
            }
        }
    }
}

// ============================================================================
// Attention (unchanged, proven): one CTA per (batch, head), fp32 scalar.
// ============================================================================
#define SST 129
#define ATTN_SMEM ((32 + 128 + 32) * SST * 4)

__global__ __launch_bounds__(256)
void attn_kernel()
{
    const int b = blockIdx.x;
    const int h = blockIdx.y;
    extern __shared__ float sm[];
    float* qs = sm;
    float* kv = sm + 32 * SST;
    float* ls = sm + (32 + 128) * SST;

    const int t  = threadIdx.x;
    const int tx = t & 31;
    const int ty = t >> 5;

    #pragma unroll
    for (int l = 0; l < 4; l++) {
        const int idx = t + l * 256;
        const int qi  = idx >> 5;
        const int dq  = (idx & 31) * 4;
        const float4 v = *reinterpret_cast<const float4*>(
            &g_q[(size_t)(b * NQ + qi) * EMB + h * HD + dq]);
        qs[qi * SST + dq + 0] = v.x; qs[qi * SST + dq + 1] = v.y;
        qs[qi * SST + dq + 2] = v.z; qs[qi * SST + dq + 3] = v.w;
    }
    #pragma unroll
    for (int l = 0; l < 16; l++) {
        const int idx = t + l * 256;
        const int kj  = idx >> 5;
        const int dq  = (idx & 31) * 4;
        const float4 v = *reinterpret_cast<const float4*>(
            &g_k[(size_t)(b * NE + kj) * EMB + h * HD + dq]);
        kv[kj * SST + dq + 0] = v.x; kv[kj * SST + dq + 1] = v.y;
        kv[kj * SST + dq + 2] = v.z; kv[kj * SST + dq + 3] = v.w;
    }
    __syncthreads();

    float acc[4][4];
    #pragma unroll
    for (int i = 0; i < 4; i++)
        #pragma unroll
        for (int j = 0; j < 4; j++) acc[i][j] = 0.f;

    for (int d = 0; d < HD; d++) {
        float a[4], bb[4];
        #pragma unroll
        for (int i = 0; i < 4; i++) a[i]  = qs[(ty + 8 * i) * SST + d];
        #pragma unroll
        for (int j = 0; j < 4; j++) bb[j] = kv[(tx + 32 * j) * SST + d];
        #pragma unroll
        for (int i = 0; i < 4; i++)
            #pragma unroll
            for (int j = 0; j < 4; j++)
                acc[i][j] = fmaf(a[i], bb[j], acc[i][j]);
    }

    const float inv_scale = 0.08838834764831845f;
    const uint8_t* pm = g_pre + (size_t)b * NQ * NE;
    #pragma unroll
    for (int i = 0; i < 4; i++) {
        const int qi = ty + 8 * i;
        #pragma unroll
        for (int j = 0; j < 4; j++) {
            const int kj = tx + 32 * j;
            ls[qi * SST + kj] = pm[qi * NE + kj] ? -1e30f : acc[i][j] * inv_scale;
        }
    }
    __syncthreads();

    #pragma unroll
    for (int l = 0; l < 16; l++) {
        const int idx = t + l * 256;
        const int kj  = idx >> 5;
        const int dq  = (idx & 31) * 4;
        const float4 v = *reinterpret_cast<const float4*>(
            &g_v[(size_t)(b * NE + kj) * EMB + h * HD + dq]);
        kv[kj * SST + dq + 0] = v.x; kv[kj * SST + dq + 1] = v.y;
        kv[kj * SST + dq + 2] = v.z; kv[kj * SST + dq + 3] = v.w;
    }

    {
        const int w    = t >> 5;
        const int lane = t & 31;
        #pragma unroll
        for (int rr = 0; rr < 4; rr++) {
            const int r = w * 4 + rr;
            float x0 = ls[r * SST + lane];
            float x1 = ls[r * SST + lane + 32];
            float x2 = ls[r * SST + lane + 64];
            float x3 = ls[r * SST + lane + 96];
            float mx = fmaxf(fmaxf(x0, x1), fmaxf(x2, x3));
            #pragma unroll
            for (int off = 16; off; off >>= 1)
                mx = fmaxf(mx, __shfl_xor_sync(0xffffffffu, mx, off));
            float e0 = (x0 <= -1e29f) ? 0.f : expf(x0 - mx);
            float e1 = (x1 <= -1e29f) ? 0.f : expf(x1 - mx);
            float e2 = (x2 <= -1e29f) ? 0.f : expf(x2 - mx);
            float e3 = (x3 <= -1e29f) ? 0.f : expf(x3 - mx);
            float s = e0 + e1 + e2 + e3;
            #pragma unroll
            for (int off = 16; off; off >>= 1)
                s += __shfl_xor_sync(0xffffffffu, s, off);
            const float inv = (s > 0.f) ? (1.f / s) : 0.f;
            ls[r * SST + lane]      = e0 * inv;
            ls[r * SST + lane + 32] = e1 * inv;
            ls[r * SST + lane + 64] = e2 * inv;
            ls[r * SST + lane + 96] = e3 * inv;
        }
    }
    __syncthreads();

    float o[4][4];
    #pragma unroll
    for (int i = 0; i < 4; i++)
        #pragma unroll
        for (int j = 0; j < 4; j++) o[i][j] = 0.f;

    for (int kj = 0; kj < NE; kj++) {
        float a[4], bb[4];
        #pragma unroll
        for (int i = 0; i < 4; i++) a[i]  = ls[(ty + 8 * i) * SST + kj];
        #pragma unroll
        for (int j = 0; j < 4; j++) bb[j] = kv[kj * SST + tx + 32 * j];
        #pragma unroll
        for (int i = 0; i < 4; i++)
            #pragma unroll
            for (int j = 0; j < 4; j++)
                o[i][j] = fmaf(a[i], bb[j], o[i][j]);
    }

    #pragma unroll
    for (int i = 0; i < 4; i++) {
        const int qi = ty + 8 * i;
        #pragma unroll
        for (int j = 0; j < 4; j++) {
            const int d = tx + 32 * j;
            g_ao[(size_t)(b * NQ + qi) * EMB + h * HD + d] = o[i][j];
        }
    }
}

// ============================================================================
extern "C" void kernel_launch(void* const* d_in, const int* in_sizes, int n_in,
                              void* d_out, int out_size)
{
    const float *entities = nullptr, *W_in = nullptr, *W_out = nullptr,
                *b_out = nullptr;
    const void  *pre_mask = nullptr, *post_mask = nullptr;
    for (int i = 0; i < n_in; i++) {
        switch (in_sizes[i]) {
            case BS * NE * IND:   entities  = (const float*)d_in[i]; break;
            case BS * NQ * NE:    pre_mask  = d_in[i];               break;
            case BS * NQ:         post_mask = d_in[i];               break;
            case 3 * EMB * IND:   W_in      = (const float*)d_in[i]; break;
            case EMB * EMB:       W_out     = (const float*)d_in[i]; break;
            case EMB:             b_out     = (const float*)d_in[i]; break;
        }
    }
    float* out = (float*)d_out;

    cudaFuncSetAttribute(attn_kernel,
                         cudaFuncAttributeMaxDynamicSharedMemorySize, ATTN_SMEM);

    // 0) normalize masks
    sniff_kernel<<<1, 256>>>(pre_mask);
    {
        uint8_t* pre_dst;  cudaGetSymbolAddress((void**)&pre_dst, g_pre);
        uint8_t* post_dst; cudaGetSymbolAddress((void**)&post_dst, g_post);
        cvt_mask_kernel<<<(BS * NQ * NE + 255) / 256, 256>>>(pre_mask, pre_dst,
                                                             BS * NQ * NE);
        cvt_mask_kernel<<<(BS * NQ + 255) / 256, 256>>>(post_mask, post_dst,
                                                        BS * NQ);
    }

    // 1) K,V projection (bf16 3x mma.sync): ent @ W_in[512:1536]^T -> g_k,g_v
    mma_gemm<IND, 0><<<dim3(8, BS), 256>>>(
        entities, W_in + (size_t)EMB * IND, nullptr, nullptr);

    // 2) Q projection -> g_q
    mma_gemm<IND, 1><<<dim3(4, (BS * NQ) / 128), 256>>>(
        entities, W_in, nullptr, nullptr);

    // 3) masked multi-head attention -> g_ao
    attn_kernel<<<dim3(BS, NH), 256, ATTN_SMEM>>>();

    // 4) output projection + bias + post_mask -> d_out
    mma_gemm<EMB, 2><<<dim3(4, (BS * NQ) / 128), 256>>>(
        nullptr, W_out, out, b_out);
}